// round 1
// baseline (speedup 1.0000x reference)
#include <cuda_runtime.h>
#include <cstdint>
#include <cstddef>

// ---------------------------------------------------------------------------
// Bidirectional GRU, B=4096 T=16 I=H=1024.
// Plan:
//   1) Precompute Gx[b,t,0:3072] = x_t @ [W_izr; W_it]^T  (shared by both dirs)
//   2) 16 sequential steps; each step:
//        Gh[d] = h[d] @ [W_hzr; W_ht]^T   (both directions, grid.z = 2)
//        fused gate kernel: r,z,htilde,nh + write output slice
// GEMMs use tf32 mma.sync.m16n8k8 (fp32 accum) for <1e-3 accuracy.
// ---------------------------------------------------------------------------

namespace {
constexpr int B_ = 4096, T_ = 16, H_ = 1024;
constexpr int N3 = 3 * H_;   // 3072 output columns
constexpr int K_ = 1024;     // reduction dim (I and H both 1024)
constexpr int BM = 128, BN = 128, BK = 32, PAD = 36;
constexpr int NK = K_ / BK;  // 32
}

// scratch (static device allocations; no runtime alloc allowed)
__device__ float g_gx[(size_t)B_ * T_ * N3];   // 805 MB
__device__ float g_gh[(size_t)2 * B_ * N3];    // 100 MB  (per-direction Gh)
__device__ float g_h[(size_t)4 * B_ * H_];     // 128 MB  ([dir][phase] ping-pong)

__device__ __forceinline__ uint32_t f2tf(float f) {
    uint32_t r;
    asm("cvt.rna.tf32.f32 %0, %1;" : "=r"(r) : "f"(f));
    return r;
}

__device__ __forceinline__ void mma_tf32(float c[4], const uint32_t a[4], const uint32_t b[2]) {
    asm volatile(
        "mma.sync.aligned.m16n8k8.row.col.f32.tf32.tf32.f32 "
        "{%0,%1,%2,%3},{%4,%5,%6,%7},{%8,%9},{%0,%1,%2,%3};"
        : "+f"(c[0]), "+f"(c[1]), "+f"(c[2]), "+f"(c[3])
        : "r"(a[0]), "r"(a[1]), "r"(a[2]), "r"(a[3]), "r"(b[0]), "r"(b[1]));
}

// C[M, 3072] = A[M,1024] @ W^T, where W rows 0..2047 come from W01, 2048..3071 from W2.
// RECUR=false: A = x (arg), M = B*T, C = g_gx.
// RECUR=true : A = g_h[dir][phase], M = B, C = g_gh[dir], grid.z = 2 directions.
template <bool RECUR>
__global__ __launch_bounds__(256, 1)
void gemm_kernel(const float* __restrict__ Aext, int phase,
                 const float* __restrict__ W01, const float* __restrict__ W2)
{
    extern __shared__ uint32_t smem[];
    uint32_t* As = smem;                    // 2 stages of BM*PAD
    uint32_t* Bs = smem + 2 * BM * PAD;     // 2 stages of BN*PAD

    const int tid  = threadIdx.x;
    const int warp = tid >> 5, lane = tid & 31;
    const int g  = lane >> 2, tg = lane & 3;
    const int wm = (warp & 1) << 6;   // warp M offset: 0/64
    const int wn = (warp >> 1) << 5;  // warp N offset: 0/32/64/96

    const int nb = blockIdx.x * BN;
    const int mb = blockIdx.y * BM;
    const int dz = blockIdx.z;

    const float* A = RECUR ? (g_h + ((size_t)dz * 2 + phase) * B_ * H_) : Aext;
    float*       C = RECUR ? (g_gh + (size_t)dz * B_ * N3) : g_gx;

    const int r0 = tid >> 3;          // 0..31
    const int c4 = (tid & 7) << 2;    // 0..28 step 4

    const float* aptr[4];
    const float* bptr[4];
#pragma unroll
    for (int i = 0; i < 4; ++i) {
        aptr[i] = A + (size_t)(mb + r0 + 32 * i) * K_ + c4;
        int n = nb + r0 + 32 * i;
        const float* w = (n < 2 * H_) ? (W01 + (size_t)n * K_)
                                      : (W2 + (size_t)(n - 2 * H_) * K_);
        bptr[i] = w + c4;
    }

    float4 va[4], vb[4];
    // prologue: stage 0
#pragma unroll
    for (int i = 0; i < 4; ++i) {
        va[i] = *reinterpret_cast<const float4*>(aptr[i]);
        vb[i] = *reinterpret_cast<const float4*>(bptr[i]);
    }
#pragma unroll
    for (int i = 0; i < 4; ++i) {
        int off = (r0 + 32 * i) * PAD + c4;
        As[off + 0] = f2tf(va[i].x); As[off + 1] = f2tf(va[i].y);
        As[off + 2] = f2tf(va[i].z); As[off + 3] = f2tf(va[i].w);
        Bs[off + 0] = f2tf(vb[i].x); Bs[off + 1] = f2tf(vb[i].y);
        Bs[off + 2] = f2tf(vb[i].z); Bs[off + 3] = f2tf(vb[i].w);
    }
    __syncthreads();

    float acc[4][4][4];
#pragma unroll
    for (int a = 0; a < 4; ++a)
#pragma unroll
        for (int b = 0; b < 4; ++b)
#pragma unroll
            for (int c = 0; c < 4; ++c) acc[a][b][c] = 0.f;

    int cur = 0;
    for (int kt = 0; kt < NK; ++kt) {
        if (kt + 1 < NK) {  // prefetch next tile into registers (overlaps MMA)
            int ko = (kt + 1) * BK;
#pragma unroll
            for (int i = 0; i < 4; ++i) {
                va[i] = *reinterpret_cast<const float4*>(aptr[i] + ko);
                vb[i] = *reinterpret_cast<const float4*>(bptr[i] + ko);
            }
        }
        const uint32_t* as = As + cur * BM * PAD;
        const uint32_t* bs = Bs + cur * BN * PAD;
#pragma unroll
        for (int ks = 0; ks < 4; ++ks) {
            const int kc = ks * 8 + tg;
            uint32_t af[4][4], bf[4][2];
#pragma unroll
            for (int mi = 0; mi < 4; ++mi) {
                int r = wm + mi * 16 + g;
                af[mi][0] = as[r * PAD + kc];
                af[mi][1] = as[(r + 8) * PAD + kc];
                af[mi][2] = as[r * PAD + kc + 4];
                af[mi][3] = as[(r + 8) * PAD + kc + 4];
            }
#pragma unroll
            for (int ni = 0; ni < 4; ++ni) {
                int n = wn + ni * 8 + g;
                bf[ni][0] = bs[n * PAD + kc];
                bf[ni][1] = bs[n * PAD + kc + 4];
            }
#pragma unroll
            for (int mi = 0; mi < 4; ++mi)
#pragma unroll
                for (int ni = 0; ni < 4; ++ni)
                    mma_tf32(acc[mi][ni], af[mi], bf[ni]);
        }
        __syncthreads();
        if (kt + 1 < NK) {
            uint32_t* dA = As + (cur ^ 1) * BM * PAD;
            uint32_t* dB = Bs + (cur ^ 1) * BN * PAD;
#pragma unroll
            for (int i = 0; i < 4; ++i) {
                int off = (r0 + 32 * i) * PAD + c4;
                dA[off + 0] = f2tf(va[i].x); dA[off + 1] = f2tf(va[i].y);
                dA[off + 2] = f2tf(va[i].z); dA[off + 3] = f2tf(va[i].w);
                dB[off + 0] = f2tf(vb[i].x); dB[off + 1] = f2tf(vb[i].y);
                dB[off + 2] = f2tf(vb[i].z); dB[off + 3] = f2tf(vb[i].w);
            }
            __syncthreads();
            cur ^= 1;
        }
    }

    // epilogue: fp32 write
#pragma unroll
    for (int mi = 0; mi < 4; ++mi) {
#pragma unroll
        for (int ni = 0; ni < 4; ++ni) {
            int r  = mb + wm + mi * 16 + g;
            int cI = nb + wn + ni * 8 + tg * 2;
            float2 v0 = make_float2(acc[mi][ni][0], acc[mi][ni][1]);
            float2 v1 = make_float2(acc[mi][ni][2], acc[mi][ni][3]);
            *reinterpret_cast<float2*>(C + (size_t)r * N3 + cI)       = v0;
            *reinterpret_cast<float2*>(C + (size_t)(r + 8) * N3 + cI) = v1;
        }
    }
}

__device__ __forceinline__ float sigmoidf_(float x) { return 1.f / (1.f + expf(-x)); }

__global__ __launch_bounds__(256)
void gate_kernel(const float* __restrict__ b_izr, const float* __restrict__ b_hzr,
                 const float* __restrict__ b_it,  const float* __restrict__ b_ht,
                 float* __restrict__ out, int s, int phase)
{
    const int d   = blockIdx.z;
    const int idx = blockIdx.x * blockDim.x + threadIdx.x;  // one float4 per thread
    const int j4  = idx << 2;
    const int b   = j4 >> 10;         // / H
    const int j   = j4 & (H_ - 1);
    const int time = (d == 0) ? s : (T_ - 1 - s);        // which x_t was consumed
    const int tout = (d == 0) ? (T_ - 1 - s) : s;        // output time index

    const float* gx = g_gx + ((size_t)b * T_ + time) * N3;
    const float* gh = g_gh + (size_t)d * B_ * N3 + (size_t)b * N3;
    const float* hp = g_h + ((size_t)d * 2 + phase) * B_ * H_ + (size_t)b * H_;
    float*       hn = g_h + ((size_t)d * 2 + (phase ^ 1)) * B_ * H_ + (size_t)b * H_;

    float4 gxr = *(const float4*)(gx + j);
    float4 gxz = *(const float4*)(gx + H_ + j);
    float4 gxt = *(const float4*)(gx + 2 * H_ + j);
    float4 ghr = *(const float4*)(gh + j);
    float4 ghz = *(const float4*)(gh + H_ + j);
    float4 ght = *(const float4*)(gh + 2 * H_ + j);
    float4 bir = *(const float4*)(b_izr + j);
    float4 biz = *(const float4*)(b_izr + H_ + j);
    float4 bhr = *(const float4*)(b_hzr + j);
    float4 bhz = *(const float4*)(b_hzr + H_ + j);
    float4 bti = *(const float4*)(b_it + j);
    float4 bth = *(const float4*)(b_ht + j);
    float4 h   = *(const float4*)(hp + j);

    float4 nh;
#define GATE(c)                                                             \
    {                                                                       \
        float rg = sigmoidf_(gxr.c + ghr.c + bir.c + bhr.c);                \
        float zg = sigmoidf_(gxz.c + ghz.c + biz.c + bhz.c);                \
        float ht = tanhf(gxt.c + bti.c + rg * (ght.c + bth.c));             \
        nh.c = zg * ht + (1.f - zg) * h.c;                                  \
    }
    GATE(x) GATE(y) GATE(z) GATE(w)
#undef GATE

    *(float4*)(hn + j) = nh;
    *(float4*)(out + ((size_t)b * T_ + tout) * (2 * H_) + (size_t)d * H_ + j) = nh;
}

__global__ void init_h(const float* __restrict__ h0, const float* __restrict__ bih0)
{
    size_t i = (size_t)blockIdx.x * blockDim.x + threadIdx.x;
    if (i < (size_t)B_ * H_) {
        g_h[i] = h0[i];                           // dir 0, phase 0
        g_h[(size_t)2 * B_ * H_ + i] = bih0[i];   // dir 1, phase 0
    }
}

extern "C" void kernel_launch(void* const* d_in, const int* in_sizes, int n_in,
                              void* d_out, int out_size)
{
    const float* x     = (const float*)d_in[0];
    const float* h0    = (const float*)d_in[1];
    const float* bih0  = (const float*)d_in[2];
    const float* W_izr = (const float*)d_in[3];
    const float* b_izr = (const float*)d_in[4];
    const float* W_hzr = (const float*)d_in[5];
    const float* b_hzr = (const float*)d_in[6];
    const float* W_it  = (const float*)d_in[7];
    const float* b_it  = (const float*)d_in[8];
    const float* W_ht  = (const float*)d_in[9];
    const float* b_ht  = (const float*)d_in[10];
    float* out = (float*)d_out;
    (void)in_sizes; (void)n_in; (void)out_size;

    const int smem_bytes = (2 * BM * PAD + 2 * BN * PAD) * 4;  // 73728 B
    cudaFuncSetAttribute(gemm_kernel<false>, cudaFuncAttributeMaxDynamicSharedMemorySize, smem_bytes);
    cudaFuncSetAttribute(gemm_kernel<true>,  cudaFuncAttributeMaxDynamicSharedMemorySize, smem_bytes);

    // h init for both directions
    init_h<<<(B_ * H_ + 255) / 256, 256>>>(h0, bih0);

    // Precompute Gx = X @ [W_izr; W_it]^T over all (b, t) at once
    gemm_kernel<false><<<dim3(N3 / BN, (B_ * T_) / BM, 1), 256, smem_bytes>>>(x, 0, W_izr, W_it);

    // 16 sequential steps, both directions per launch
    int phase = 0;
    for (int s = 0; s < T_; ++s) {
        gemm_kernel<true><<<dim3(N3 / BN, B_ / BM, 2), 256, smem_bytes>>>(nullptr, phase, W_hzr, W_ht);
        gate_kernel<<<dim3((B_ * H_) / (256 * 4), 1, 2), 256>>>(b_izr, b_hzr, b_it, b_ht, out, s, phase);
        phase ^= 1;
    }
}

// round 3
// speedup vs baseline: 1.6002x; 1.6002x over previous
#include <cuda_runtime.h>
#include <cuda_fp16.h>
#include <cstdint>
#include <cstddef>

// ---------------------------------------------------------------------------
// Bidirectional GRU, B=4096 T=16 I=H=1024.
//   Gx = X @ [W_izr; W_it]^T   (one big GEMM, shared by both directions)
//   per step: Gh[d] = h[d] @ [W_hzr; W_ht]^T  (grid.z = 2), fused gate kernel.
// GEMM: fp16 inputs (pre-converted), fp32 accum, mma.sync.m16n8k16 +
// ldmatrix.x4 + cp.async 4-stage pipeline. fp16 has the same 10-bit mantissa
// as tf32 but 2x the legacy tensor-core rate. (tcgen05 unavailable: harness
// compiles at virtual arch compute_103, no 'a' features.)
// ---------------------------------------------------------------------------

namespace {
constexpr int B_ = 4096, T_ = 16, H_ = 1024;
constexpr int N3 = 3 * H_, K_ = 1024;
constexpr int BM = 128, BN = 256, BK = 32;   // CTA tile; BK in halfs
constexpr int NKT = K_ / BK;                 // 32 k-iterations
constexpr int NST = 4;                       // cp.async stages
constexpr int ROWB = 80;                     // smem row pitch bytes (64B data + 16B pad)
constexpr int A_BYTES = BM * ROWB;           // 10240
constexpr int B_BYTES = BN * ROWB;           // 20480
constexpr int STAGE = A_BYTES + B_BYTES;     // 30720
constexpr int SMEM_BYTES = NST * STAGE;      // 122880
}

// scratch (static device allocations; no runtime alloc allowed)
__device__ __align__(256) float  g_gx[(size_t)B_ * T_ * N3];    // x-projections
__device__ __align__(256) float  g_gh[(size_t)2 * B_ * N3];     // h-projections
__device__ __align__(256) float  g_h [(size_t)4 * B_ * H_];     // fp32 h ping-pong
__device__ __align__(256) __half g_h16[(size_t)4 * B_ * H_];    // fp16 mirror of h
__device__ __align__(256) __half g_x16[(size_t)B_ * T_ * K_];   // fp16 x
__device__ __align__(256) __half g_wx16[(size_t)N3 * K_];       // [W_izr; W_it] fp16
__device__ __align__(256) __half g_wh16[(size_t)N3 * K_];       // [W_hzr; W_ht] fp16

// ------------------------------ PTX helpers --------------------------------
__device__ __forceinline__ uint32_t smem_u32(const void* p) {
    uint32_t a;
    asm("{.reg .u64 t; cvta.to.shared.u64 t, %1; cvt.u32.u64 %0, t;}" : "=r"(a) : "l"(p));
    return a;
}
__device__ __forceinline__ void cp16(uint32_t d, const void* s) {
    asm volatile("cp.async.cg.shared.global [%0], [%1], 16;" :: "r"(d), "l"(s));
}
__device__ __forceinline__ void cp_commit() { asm volatile("cp.async.commit_group;"); }
template <int N>
__device__ __forceinline__ void cp_wait() { asm volatile("cp.async.wait_group %0;" :: "n"(N)); }

__device__ __forceinline__ void ldsm4(uint32_t& r0, uint32_t& r1, uint32_t& r2, uint32_t& r3,
                                      uint32_t a) {
    asm volatile("ldmatrix.sync.aligned.m8n8.x4.shared.b16 {%0,%1,%2,%3}, [%4];"
                 : "=r"(r0), "=r"(r1), "=r"(r2), "=r"(r3) : "r"(a));
}
__device__ __forceinline__ void mma16816(float c[4], const uint32_t a[4], const uint32_t b[2]) {
    asm volatile(
        "mma.sync.aligned.m16n8k16.row.col.f32.f16.f16.f32 "
        "{%0,%1,%2,%3},{%4,%5,%6,%7},{%8,%9},{%0,%1,%2,%3};"
        : "+f"(c[0]), "+f"(c[1]), "+f"(c[2]), "+f"(c[3])
        : "r"(a[0]), "r"(a[1]), "r"(a[2]), "r"(a[3]), "r"(b[0]), "r"(b[1]));
}

// ------------------------------ GEMM kernel --------------------------------
// C[mb:mb+128, n0:n0+256] = A[*, 0:1024] @ W[n, 0:1024]^T  (A, W fp16; C fp32)
// recur=1: A rows from g_h16[(dz*2+phase)*B_ + mb ...]; C += dz*B_*N3.
__global__ __launch_bounds__(256, 1)
void gemm_f16(const __half* __restrict__ Ag, const __half* __restrict__ Wg,
              float* __restrict__ Cb, int phase, int recur)
{
    extern __shared__ __align__(128) char smem[];
    const uint32_t sb = smem_u32(smem);
    const int tid = threadIdx.x, warp = tid >> 5, lane = tid & 31;
    const int n0 = blockIdx.x * BN, mb = blockIdx.y * BM, dz = blockIdx.z;

    const __half* A = Ag + (recur ? (size_t)((dz * 2 + phase) * B_ + mb) * K_
                                  : (size_t)mb * K_);
    const __half* W = Wg + (size_t)n0 * K_;
    float* C = Cb + (size_t)dz * B_ * N3;

    // cp.async assignments: A: 2 x 16B per thread, B: 4 x 16B per thread
    const int ar = tid >> 1, ac2 = (tid & 1) * 2;
    const __half* aSrc = A + (size_t)ar * K_ + ac2 * 8;
    const __half* bSrc = W + (size_t)tid * K_;
    const uint32_t aDst = sb + ar * ROWB + ac2 * 16;
    const uint32_t bDst = sb + A_BYTES + tid * ROWB;

    // ldmatrix per-lane base addresses (within stage 0)
    const int wm = (warp & 1) * 64, wn = (warp >> 1) * 64;
    const uint32_t aFrag = sb + (uint32_t)(wm + (lane & 15)) * ROWB + ((lane >> 4) & 1) * 16;
    const uint32_t bFrag = sb + A_BYTES +
        (uint32_t)(wn + ((lane >> 4) & 1) * 8 + (lane & 7)) * ROWB + ((lane >> 3) & 1) * 16;

    float acc[4][8][4];
#pragma unroll
    for (int a = 0; a < 4; ++a)
#pragma unroll
        for (int b = 0; b < 8; ++b)
#pragma unroll
            for (int c = 0; c < 4; ++c) acc[a][b][c] = 0.f;

#define FILL(S, KT)                                                              \
    {                                                                            \
        uint32_t d = aDst + (S) * STAGE;                                         \
        const __half* p = aSrc + (KT) * BK;                                      \
        cp16(d, p); cp16(d + 16, p + 8);                                         \
        d = bDst + (S) * STAGE;                                                  \
        p = bSrc + (KT) * BK;                                                    \
        cp16(d, p); cp16(d + 16, p + 8); cp16(d + 32, p + 16); cp16(d + 48, p + 24); \
    }

    // prologue: stages 0..NST-2
#pragma unroll
    for (int s = 0; s < NST - 1; ++s) { FILL(s, s); cp_commit(); }

    for (int kt = 0; kt < NKT; ++kt) {
        const int s = kt & (NST - 1);
        cp_wait<NST - 2>();
        __syncthreads();
        if (kt + NST - 1 < NKT) FILL((kt + NST - 1) & (NST - 1), kt + NST - 1);
        cp_commit();

        const uint32_t aS = aFrag + s * STAGE;
        const uint32_t bS = bFrag + s * STAGE;
#pragma unroll
        for (int ks = 0; ks < 2; ++ks) {
            uint32_t af[4][4], bf[8][2];
#pragma unroll
            for (int mi = 0; mi < 4; ++mi)
                ldsm4(af[mi][0], af[mi][1], af[mi][2], af[mi][3],
                      aS + mi * 16 * ROWB + ks * 32);
#pragma unroll
            for (int nj = 0; nj < 4; ++nj)
                ldsm4(bf[2 * nj][0], bf[2 * nj][1], bf[2 * nj + 1][0], bf[2 * nj + 1][1],
                      bS + nj * 16 * ROWB + ks * 32);
#pragma unroll
            for (int mi = 0; mi < 4; ++mi)
#pragma unroll
                for (int ni = 0; ni < 8; ++ni)
                    mma16816(acc[mi][ni], af[mi], bf[ni]);
        }
    }
#undef FILL

    // epilogue: fp32 stores
    float* crow = C + (size_t)(mb + wm + (lane >> 2)) * N3 + n0 + wn + (lane & 3) * 2;
#pragma unroll
    for (int mi = 0; mi < 4; ++mi) {
#pragma unroll
        for (int ni = 0; ni < 8; ++ni) {
            *reinterpret_cast<float2*>(crow + (size_t)(mi * 16) * N3 + ni * 8) =
                make_float2(acc[mi][ni][0], acc[mi][ni][1]);
            *reinterpret_cast<float2*>(crow + (size_t)(mi * 16 + 8) * N3 + ni * 8) =
                make_float2(acc[mi][ni][2], acc[mi][ni][3]);
        }
    }
}

// ------------------------------ gate kernel --------------------------------
__device__ __forceinline__ float sigmoidf_(float x) { return 1.f / (1.f + expf(-x)); }

__global__ __launch_bounds__(256)
void gate_kernel(const float* __restrict__ b_izr, const float* __restrict__ b_hzr,
                 const float* __restrict__ b_it,  const float* __restrict__ b_ht,
                 float* __restrict__ out, int s, int phase)
{
    const int d   = blockIdx.z;
    const int idx = blockIdx.x * blockDim.x + threadIdx.x;
    const int j4  = idx << 2;
    const int b   = j4 >> 10;
    const int j   = j4 & (H_ - 1);
    const int time = (d == 0) ? s : (T_ - 1 - s);
    const int tout = (d == 0) ? (T_ - 1 - s) : s;

    const float* gx = g_gx + ((size_t)b * T_ + time) * N3;
    const float* gh = g_gh + (size_t)d * B_ * N3 + (size_t)b * N3;
    const float* hp = g_h + ((size_t)d * 2 + phase) * B_ * H_ + (size_t)b * H_;
    const size_t hoff = ((size_t)d * 2 + (phase ^ 1)) * B_ * H_ + (size_t)b * H_ + j;

    float4 gxr = *(const float4*)(gx + j);
    float4 gxz = *(const float4*)(gx + H_ + j);
    float4 gxt = *(const float4*)(gx + 2 * H_ + j);
    float4 ghr = *(const float4*)(gh + j);
    float4 ghz = *(const float4*)(gh + H_ + j);
    float4 ght = *(const float4*)(gh + 2 * H_ + j);
    float4 bir = *(const float4*)(b_izr + j);
    float4 biz = *(const float4*)(b_izr + H_ + j);
    float4 bhr = *(const float4*)(b_hzr + j);
    float4 bhz = *(const float4*)(b_hzr + H_ + j);
    float4 bti = *(const float4*)(b_it + j);
    float4 bth = *(const float4*)(b_ht + j);
    float4 h   = *(const float4*)(hp + j);

    float4 nh;
#define GATE(c)                                                             \
    {                                                                       \
        float rg = sigmoidf_(gxr.c + ghr.c + bir.c + bhr.c);                \
        float zg = sigmoidf_(gxz.c + ghz.c + biz.c + bhz.c);                \
        float ht = tanhf(gxt.c + bti.c + rg * (ght.c + bth.c));             \
        nh.c = zg * ht + (1.f - zg) * h.c;                                  \
    }
    GATE(x) GATE(y) GATE(z) GATE(w)
#undef GATE

    *(float4*)(g_h + hoff) = nh;
    __half2 p0 = __floats2half2_rn(nh.x, nh.y);
    __half2 p1 = __floats2half2_rn(nh.z, nh.w);
    uint2 u; u.x = *reinterpret_cast<uint32_t*>(&p0); u.y = *reinterpret_cast<uint32_t*>(&p1);
    *reinterpret_cast<uint2*>(g_h16 + hoff) = u;
    *(float4*)(out + ((size_t)b * T_ + tout) * (2 * H_) + (size_t)d * H_ + j) = nh;
}

// ------------------------------ small kernels ------------------------------
__global__ void cvt16(const float* __restrict__ s, __half* __restrict__ d, int n4)
{
    int i = blockIdx.x * blockDim.x + threadIdx.x;
    if (i < n4) {
        float4 v = reinterpret_cast<const float4*>(s)[i];
        __half2 p0 = __floats2half2_rn(v.x, v.y);
        __half2 p1 = __floats2half2_rn(v.z, v.w);
        uint2 u; u.x = *reinterpret_cast<uint32_t*>(&p0); u.y = *reinterpret_cast<uint32_t*>(&p1);
        reinterpret_cast<uint2*>(d)[i] = u;
    }
}

__global__ void init_h(const float* __restrict__ h0, const float* __restrict__ bih0)
{
    size_t i = (size_t)blockIdx.x * blockDim.x + threadIdx.x;
    if (i < (size_t)B_ * H_) {
        float a = h0[i], b = bih0[i];
        g_h[i] = a;
        g_h[(size_t)2 * B_ * H_ + i] = b;
        g_h16[i] = __float2half_rn(a);
        g_h16[(size_t)2 * B_ * H_ + i] = __float2half_rn(b);
    }
}

// ------------------------------ host side ----------------------------------
extern "C" void kernel_launch(void* const* d_in, const int* in_sizes, int n_in,
                              void* d_out, int out_size)
{
    const float* x     = (const float*)d_in[0];
    const float* h0    = (const float*)d_in[1];
    const float* bih0  = (const float*)d_in[2];
    const float* W_izr = (const float*)d_in[3];
    const float* b_izr = (const float*)d_in[4];
    const float* W_hzr = (const float*)d_in[5];
    const float* b_hzr = (const float*)d_in[6];
    const float* W_it  = (const float*)d_in[7];
    const float* b_it  = (const float*)d_in[8];
    const float* W_ht  = (const float*)d_in[9];
    const float* b_ht  = (const float*)d_in[10];
    float* out = (float*)d_out;
    (void)in_sizes; (void)n_in; (void)out_size;

    void *p_gx = nullptr, *p_gh = nullptr, *p_x16 = nullptr, *p_h16 = nullptr,
         *p_wx = nullptr, *p_wh = nullptr;
    cudaGetSymbolAddress(&p_gx, g_gx);
    cudaGetSymbolAddress(&p_gh, g_gh);
    cudaGetSymbolAddress(&p_x16, g_x16);
    cudaGetSymbolAddress(&p_h16, g_h16);
    cudaGetSymbolAddress(&p_wx, g_wx16);
    cudaGetSymbolAddress(&p_wh, g_wh16);

    cudaFuncSetAttribute(gemm_f16, cudaFuncAttributeMaxDynamicSharedMemorySize, SMEM_BYTES);

    // fp16 conversions
    const int WN4 = 2 * H_ * K_ / 4, WN4b = H_ * K_ / 4, XN4 = B_ * T_ * K_ / 4;
    cvt16<<<(WN4 + 255) / 256, 256>>>(W_izr, (__half*)p_wx, WN4);
    cvt16<<<(WN4b + 255) / 256, 256>>>(W_it, (__half*)p_wx + (size_t)2 * H_ * K_, WN4b);
    cvt16<<<(WN4 + 255) / 256, 256>>>(W_hzr, (__half*)p_wh, WN4);
    cvt16<<<(WN4b + 255) / 256, 256>>>(W_ht, (__half*)p_wh + (size_t)2 * H_ * K_, WN4b);
    cvt16<<<(XN4 + 255) / 256, 256>>>(x, (__half*)p_x16, XN4);
    init_h<<<(B_ * H_ + 255) / 256, 256>>>(h0, bih0);

    // Gx = X @ [W_izr; W_it]^T over all (b, t)
    gemm_f16<<<dim3(N3 / BN, (B_ * T_) / BM, 1), 256, SMEM_BYTES>>>(
        (const __half*)p_x16, (const __half*)p_wx, (float*)p_gx, 0, 0);

    // 16 sequential steps, both directions per launch
    int phase = 0;
    for (int s = 0; s < T_; ++s) {
        gemm_f16<<<dim3(N3 / BN, B_ / BM, 2), 256, SMEM_BYTES>>>(
            (const __half*)p_h16, (const __half*)p_wh, (float*)p_gh, phase, 1);
        gate_kernel<<<dim3((B_ * H_) / (256 * 4), 1, 2), 256>>>(
            b_izr, b_hzr, b_it, b_ht, out, s, phase);
        phase ^= 1;
    }
}

// round 4
// speedup vs baseline: 2.3813x; 1.4881x over previous
#include <cuda_runtime.h>
#include <cuda_fp16.h>
#include <cstdint>
#include <cstddef>

// ---------------------------------------------------------------------------
// Bidirectional GRU, B=4096 T=16 I=H=1024.
//   Gx = X @ [W_izr; W_it]^T   (one big GEMM, shared by both directions)
//   per step: Gh[d] = h[d] @ [W_hzr; W_ht]^T  (grid.z = 2), fused gate kernel.
// GEMM: fp16 in / fp16 out (fp32 accum), mma.sync.m16n8k16 + ldmatrix.x4 +
// cp.async, 128x128 CTA tile, BK=64, 3 stages, 2 CTAs/SM for latency hiding.
// ---------------------------------------------------------------------------

namespace {
constexpr int B_ = 4096, T_ = 16, H_ = 1024;
constexpr int N3 = 3 * H_, K_ = 1024;
constexpr int BM = 128, BN = 128, BK = 64;   // CTA tile; BK in halfs
constexpr int NKT = K_ / BK;                 // 16 k-iterations
constexpr int NST = 3;                       // cp.async stages
constexpr int ROWB = 144;                    // smem row pitch bytes (128B data + 16B pad)
constexpr int A_BYTES = BM * ROWB;           // 18432
constexpr int STAGE = 2 * A_BYTES;           // 36864 (A + B)
constexpr int SMEM_BYTES = NST * STAGE;      // 110592
}

// scratch (static device allocations; no runtime alloc allowed)
__device__ __align__(256) __half g_gx16[(size_t)B_ * T_ * N3];  // x-projections (fp16)
__device__ __align__(256) __half g_gh16[(size_t)2 * B_ * N3];   // h-projections (fp16)
__device__ __align__(256) float  g_h [(size_t)4 * B_ * H_];     // fp32 h ping-pong
__device__ __align__(256) __half g_h16[(size_t)4 * B_ * H_];    // fp16 mirror of h
__device__ __align__(256) __half g_x16[(size_t)B_ * T_ * K_];   // fp16 x
__device__ __align__(256) __half g_wx16[(size_t)N3 * K_];       // [W_izr; W_it] fp16
__device__ __align__(256) __half g_wh16[(size_t)N3 * K_];       // [W_hzr; W_ht] fp16

// ------------------------------ PTX helpers --------------------------------
__device__ __forceinline__ uint32_t smem_u32(const void* p) {
    uint32_t a;
    asm("{.reg .u64 t; cvta.to.shared.u64 t, %1; cvt.u32.u64 %0, t;}" : "=r"(a) : "l"(p));
    return a;
}
__device__ __forceinline__ void cp16(uint32_t d, const void* s) {
    asm volatile("cp.async.cg.shared.global [%0], [%1], 16;" :: "r"(d), "l"(s));
}
__device__ __forceinline__ void cp_commit() { asm volatile("cp.async.commit_group;"); }
template <int N>
__device__ __forceinline__ void cp_wait() { asm volatile("cp.async.wait_group %0;" :: "n"(N)); }

__device__ __forceinline__ void ldsm4(uint32_t& r0, uint32_t& r1, uint32_t& r2, uint32_t& r3,
                                      uint32_t a) {
    asm volatile("ldmatrix.sync.aligned.m8n8.x4.shared.b16 {%0,%1,%2,%3}, [%4];"
                 : "=r"(r0), "=r"(r1), "=r"(r2), "=r"(r3) : "r"(a));
}
__device__ __forceinline__ void mma16816(float c[4], const uint32_t a[4], const uint32_t b[2]) {
    asm volatile(
        "mma.sync.aligned.m16n8k16.row.col.f32.f16.f16.f32 "
        "{%0,%1,%2,%3},{%4,%5,%6,%7},{%8,%9},{%0,%1,%2,%3};"
        : "+f"(c[0]), "+f"(c[1]), "+f"(c[2]), "+f"(c[3])
        : "r"(a[0]), "r"(a[1]), "r"(a[2]), "r"(a[3]), "r"(b[0]), "r"(b[1]));
}

// ------------------------------ GEMM kernel --------------------------------
// C[mb:mb+128, n0:n0+128] = A @ W[n,:]^T  (A, W fp16; C fp16, fp32 accum)
__global__ __launch_bounds__(256, 2)
void gemm_f16(const __half* __restrict__ Ag, const __half* __restrict__ Wg,
              __half* __restrict__ Cb, int phase, int recur)
{
    extern __shared__ __align__(128) char smem[];
    const uint32_t sb = smem_u32(smem);
    const int tid = threadIdx.x, warp = tid >> 5, lane = tid & 31;
    const int n0 = blockIdx.x * BN, mb = blockIdx.y * BM, dz = blockIdx.z;

    const __half* A = Ag + (recur ? (size_t)((dz * 2 + phase) * B_ + mb) * K_
                                  : (size_t)mb * K_);
    const __half* W = Wg + (size_t)n0 * K_;
    __half* C = Cb + (size_t)dz * B_ * N3;

    // warp tile: 64 x 32  (warp grid 2 x 4)
    const int wm = (warp & 1) * 64, wn = (warp >> 1) * 32;
    const uint32_t aFrag = sb + (uint32_t)(wm + (lane & 15)) * ROWB + ((lane >> 4) & 1) * 16;
    const uint32_t bFrag = sb + A_BYTES +
        (uint32_t)(wn + ((lane >> 4) & 1) * 8 + (lane & 7)) * ROWB + ((lane >> 3) & 1) * 16;

    float acc[4][4][4];
#pragma unroll
    for (int a = 0; a < 4; ++a)
#pragma unroll
        for (int b = 0; b < 4; ++b)
#pragma unroll
            for (int c = 0; c < 4; ++c) acc[a][b][c] = 0.f;

    // fill: 128 rows x 8 chunks(16B) each for A and B; 4 per thread each
#define FILL(S, KT)                                                           \
    {                                                                         \
        _Pragma("unroll")                                                     \
        for (int i = 0; i < 4; ++i) {                                         \
            int c = tid + 256 * i;                                            \
            int row = c >> 3, col = c & 7;                                    \
            uint32_t d = sb + (S) * STAGE + row * ROWB + col * 16;            \
            cp16(d, A + (size_t)row * K_ + (KT) * BK + col * 8);              \
            cp16(d + A_BYTES, W + (size_t)row * K_ + (KT) * BK + col * 8);    \
        }                                                                     \
    }

#pragma unroll
    for (int s = 0; s < NST - 1; ++s) { FILL(s, s); cp_commit(); }

    int st = 0;
    for (int kt = 0; kt < NKT; ++kt) {
        cp_wait<NST - 2>();
        __syncthreads();
        if (kt + NST - 1 < NKT) {
            int fs = st + 2; if (fs >= NST) fs -= NST;
            FILL(fs, kt + NST - 1);
        }
        cp_commit();

        const uint32_t aS = aFrag + st * STAGE;
        const uint32_t bS = bFrag + st * STAGE;
#pragma unroll
        for (int ks = 0; ks < 4; ++ks) {
            uint32_t af[4][4], bf[4][2];
#pragma unroll
            for (int mi = 0; mi < 4; ++mi)
                ldsm4(af[mi][0], af[mi][1], af[mi][2], af[mi][3],
                      aS + mi * 16 * ROWB + ks * 32);
#pragma unroll
            for (int nj = 0; nj < 2; ++nj)
                ldsm4(bf[2 * nj][0], bf[2 * nj][1], bf[2 * nj + 1][0], bf[2 * nj + 1][1],
                      bS + nj * 16 * ROWB + ks * 32);
#pragma unroll
            for (int mi = 0; mi < 4; ++mi)
#pragma unroll
                for (int ni = 0; ni < 4; ++ni)
                    mma16816(acc[mi][ni], af[mi], bf[ni]);
        }
        if (++st == NST) st = 0;
    }
#undef FILL

    // epilogue: fp16 stores (half2 per fragment row-pair)
    __half* crow = C + (size_t)(mb + wm + (lane >> 2)) * N3 + n0 + wn + (lane & 3) * 2;
#pragma unroll
    for (int mi = 0; mi < 4; ++mi) {
#pragma unroll
        for (int ni = 0; ni < 4; ++ni) {
            *reinterpret_cast<__half2*>(crow + (size_t)(mi * 16) * N3 + ni * 8) =
                __floats2half2_rn(acc[mi][ni][0], acc[mi][ni][1]);
            *reinterpret_cast<__half2*>(crow + (size_t)(mi * 16 + 8) * N3 + ni * 8) =
                __floats2half2_rn(acc[mi][ni][2], acc[mi][ni][3]);
        }
    }
}

// ------------------------------ gate kernel --------------------------------
__device__ __forceinline__ float sigmoidf_(float x) { return 1.f / (1.f + expf(-x)); }

__global__ __launch_bounds__(256)
void gate_kernel(const float* __restrict__ b_izr, const float* __restrict__ b_hzr,
                 const float* __restrict__ b_it,  const float* __restrict__ b_ht,
                 float* __restrict__ out, int s, int phase)
{
    const int d   = blockIdx.z;
    const int idx = blockIdx.x * blockDim.x + threadIdx.x;
    const int j4  = idx << 2;
    const int b   = j4 >> 10;
    const int j   = j4 & (H_ - 1);
    const int time = (d == 0) ? s : (T_ - 1 - s);
    const int tout = (d == 0) ? (T_ - 1 - s) : s;

    const __half* gx = g_gx16 + ((size_t)b * T_ + time) * N3;
    const __half* gh = g_gh16 + (size_t)d * B_ * N3 + (size_t)b * N3;
    const float*  hp = g_h + ((size_t)d * 2 + phase) * B_ * H_ + (size_t)b * H_;
    const size_t hoff = ((size_t)d * 2 + (phase ^ 1)) * B_ * H_ + (size_t)b * H_ + j;

#define LDH4(p) (*reinterpret_cast<const uint2*>(p))
    uint2 uxr = LDH4(gx + j),          uxz = LDH4(gx + H_ + j),      uxt = LDH4(gx + 2 * H_ + j);
    uint2 uhr = LDH4(gh + j),          uhz = LDH4(gh + H_ + j),      uht = LDH4(gh + 2 * H_ + j);
#undef LDH4
    float4 bir = *(const float4*)(b_izr + j);
    float4 biz = *(const float4*)(b_izr + H_ + j);
    float4 bhr = *(const float4*)(b_hzr + j);
    float4 bhz = *(const float4*)(b_hzr + H_ + j);
    float4 bti = *(const float4*)(b_it + j);
    float4 bth = *(const float4*)(b_ht + j);
    float4 h   = *(const float4*)(hp + j);

    float2 xr0 = __half22float2(*reinterpret_cast<__half2*>(&uxr.x));
    float2 xr1 = __half22float2(*reinterpret_cast<__half2*>(&uxr.y));
    float2 xz0 = __half22float2(*reinterpret_cast<__half2*>(&uxz.x));
    float2 xz1 = __half22float2(*reinterpret_cast<__half2*>(&uxz.y));
    float2 xt0 = __half22float2(*reinterpret_cast<__half2*>(&uxt.x));
    float2 xt1 = __half22float2(*reinterpret_cast<__half2*>(&uxt.y));
    float2 hr0 = __half22float2(*reinterpret_cast<__half2*>(&uhr.x));
    float2 hr1 = __half22float2(*reinterpret_cast<__half2*>(&uhr.y));
    float2 hz0 = __half22float2(*reinterpret_cast<__half2*>(&uhz.x));
    float2 hz1 = __half22float2(*reinterpret_cast<__half2*>(&uhz.y));
    float2 ht0 = __half22float2(*reinterpret_cast<__half2*>(&uht.x));
    float2 ht1 = __half22float2(*reinterpret_cast<__half2*>(&uht.y));

    float4 nh;
#define GATE(c, GXR, GHR, GXZ, GHZ, GXT, GHT)                               \
    {                                                                       \
        float rg = sigmoidf_(GXR + GHR + bir.c + bhr.c);                    \
        float zg = sigmoidf_(GXZ + GHZ + biz.c + bhz.c);                    \
        float ht = tanhf(GXT + bti.c + rg * (GHT + bth.c));                 \
        nh.c = zg * ht + (1.f - zg) * h.c;                                  \
    }
    GATE(x, xr0.x, hr0.x, xz0.x, hz0.x, xt0.x, ht0.x)
    GATE(y, xr0.y, hr0.y, xz0.y, hz0.y, xt0.y, ht0.y)
    GATE(z, xr1.x, hr1.x, xz1.x, hz1.x, xt1.x, ht1.x)
    GATE(w, xr1.y, hr1.y, xz1.y, hz1.y, xt1.y, ht1.y)
#undef GATE

    *(float4*)(g_h + hoff) = nh;
    __half2 p0 = __floats2half2_rn(nh.x, nh.y);
    __half2 p1 = __floats2half2_rn(nh.z, nh.w);
    uint2 u; u.x = *reinterpret_cast<uint32_t*>(&p0); u.y = *reinterpret_cast<uint32_t*>(&p1);
    *reinterpret_cast<uint2*>(g_h16 + hoff) = u;
    *(float4*)(out + ((size_t)b * T_ + tout) * (2 * H_) + (size_t)d * H_ + j) = nh;
}

// ------------------------------ small kernels ------------------------------
__global__ void cvt16(const float* __restrict__ s, __half* __restrict__ d, int n4)
{
    int i = blockIdx.x * blockDim.x + threadIdx.x;
    if (i < n4) {
        float4 v = reinterpret_cast<const float4*>(s)[i];
        __half2 p0 = __floats2half2_rn(v.x, v.y);
        __half2 p1 = __floats2half2_rn(v.z, v.w);
        uint2 u; u.x = *reinterpret_cast<uint32_t*>(&p0); u.y = *reinterpret_cast<uint32_t*>(&p1);
        reinterpret_cast<uint2*>(d)[i] = u;
    }
}

__global__ void init_h(const float* __restrict__ h0, const float* __restrict__ bih0)
{
    size_t i = (size_t)blockIdx.x * blockDim.x + threadIdx.x;
    if (i < (size_t)B_ * H_) {
        float a = h0[i], b = bih0[i];
        g_h[i] = a;
        g_h[(size_t)2 * B_ * H_ + i] = b;
        g_h16[i] = __float2half_rn(a);
        g_h16[(size_t)2 * B_ * H_ + i] = __float2half_rn(b);
    }
}

// ------------------------------ host side ----------------------------------
extern "C" void kernel_launch(void* const* d_in, const int* in_sizes, int n_in,
                              void* d_out, int out_size)
{
    const float* x     = (const float*)d_in[0];
    const float* h0    = (const float*)d_in[1];
    const float* bih0  = (const float*)d_in[2];
    const float* W_izr = (const float*)d_in[3];
    const float* b_izr = (const float*)d_in[4];
    const float* W_hzr = (const float*)d_in[5];
    const float* b_hzr = (const float*)d_in[6];
    const float* W_it  = (const float*)d_in[7];
    const float* b_it  = (const float*)d_in[8];
    const float* W_ht  = (const float*)d_in[9];
    const float* b_ht  = (const float*)d_in[10];
    float* out = (float*)d_out;
    (void)in_sizes; (void)n_in; (void)out_size;

    void *p_gx = nullptr, *p_gh = nullptr, *p_x16 = nullptr, *p_h16 = nullptr,
         *p_wx = nullptr, *p_wh = nullptr;
    cudaGetSymbolAddress(&p_gx, g_gx16);
    cudaGetSymbolAddress(&p_gh, g_gh16);
    cudaGetSymbolAddress(&p_x16, g_x16);
    cudaGetSymbolAddress(&p_h16, g_h16);
    cudaGetSymbolAddress(&p_wx, g_wx16);
    cudaGetSymbolAddress(&p_wh, g_wh16);

    cudaFuncSetAttribute(gemm_f16, cudaFuncAttributeMaxDynamicSharedMemorySize, SMEM_BYTES);

    // fp16 conversions
    const int WN4 = 2 * H_ * K_ / 4, WN4b = H_ * K_ / 4, XN4 = B_ * T_ * K_ / 4;
    cvt16<<<(WN4 + 255) / 256, 256>>>(W_izr, (__half*)p_wx, WN4);
    cvt16<<<(WN4b + 255) / 256, 256>>>(W_it, (__half*)p_wx + (size_t)2 * H_ * K_, WN4b);
    cvt16<<<(WN4 + 255) / 256, 256>>>(W_hzr, (__half*)p_wh, WN4);
    cvt16<<<(WN4b + 255) / 256, 256>>>(W_ht, (__half*)p_wh + (size_t)2 * H_ * K_, WN4b);
    cvt16<<<(XN4 + 255) / 256, 256>>>(x, (__half*)p_x16, XN4);
    init_h<<<(B_ * H_ + 255) / 256, 256>>>(h0, bih0);

    // Gx = X @ [W_izr; W_it]^T over all (b, t)
    gemm_f16<<<dim3(N3 / BN, (B_ * T_) / BM, 1), 256, SMEM_BYTES>>>(
        (const __half*)p_x16, (const __half*)p_wx, (__half*)p_gx, 0, 0);

    // 16 sequential steps, both directions per launch
    int phase = 0;
    for (int s = 0; s < T_; ++s) {
        gemm_f16<<<dim3(N3 / BN, B_ / BM, 2), 256, SMEM_BYTES>>>(
            (const __half*)p_h16, (const __half*)p_wh, (__half*)p_gh, phase, 1);
        gate_kernel<<<dim3((B_ * H_) / (256 * 4), 1, 2), 256>>>(
            b_izr, b_hzr, b_it, b_ht, out, s, phase);
        phase ^= 1;
    }
}

// round 5
// speedup vs baseline: 2.4191x; 1.0159x over previous
#include <cuda_runtime.h>
#include <cuda_fp16.h>
#include <cstdint>
#include <cstddef>

// ---------------------------------------------------------------------------
// Bidirectional GRU, B=4096 T=16 I=H=1024.
//   Gx = X @ [W_izr; W_it]^T   (one big GEMM, shared by both directions)
//   per step: Gh[d] = h[d] @ [W_hzr; W_ht]^T  (grid.z = 2), fused gate kernel.
// GEMM: fp16 in/out (fp32 accum), mma.sync.m16n8k16 + ldmatrix.x4 + cp.async.
// 128x128 CTA tile, 4 warps with 64x64 warp tiles (minimizes smem fragment
// traffic per MAC: 2(WM+WN)/(WM*WN)), BK=64, 3 stages, 2 CTAs/SM.
// ---------------------------------------------------------------------------

namespace {
constexpr int B_ = 4096, T_ = 16, H_ = 1024;
constexpr int N3 = 3 * H_, K_ = 1024;
constexpr int BM = 128, BN = 128, BK = 64;   // CTA tile; BK in halfs
constexpr int NKT = K_ / BK;                 // 16 k-iterations
constexpr int NST = 3;                       // cp.async stages
constexpr int ROWB = 144;                    // smem row pitch (128B data + 16B pad)
constexpr int A_BYTES = BM * ROWB;           // 18432
constexpr int STAGE = 2 * A_BYTES;           // 36864 (A + B)
constexpr int SMEM_BYTES = NST * STAGE;      // 110592
}

// scratch (static device allocations; no runtime alloc allowed)
__device__ __align__(256) __half g_gx16[(size_t)B_ * T_ * N3];  // x-projections (fp16)
__device__ __align__(256) __half g_gh16[(size_t)2 * B_ * N3];   // h-projections (fp16)
__device__ __align__(256) float  g_h [(size_t)4 * B_ * H_];     // fp32 h ping-pong
__device__ __align__(256) __half g_h16[(size_t)4 * B_ * H_];    // fp16 mirror of h
__device__ __align__(256) __half g_x16[(size_t)B_ * T_ * K_];   // fp16 x
__device__ __align__(256) __half g_wx16[(size_t)N3 * K_];       // [W_izr; W_it] fp16
__device__ __align__(256) __half g_wh16[(size_t)N3 * K_];       // [W_hzr; W_ht] fp16

// ------------------------------ PTX helpers --------------------------------
__device__ __forceinline__ uint32_t smem_u32(const void* p) {
    uint32_t a;
    asm("{.reg .u64 t; cvta.to.shared.u64 t, %1; cvt.u32.u64 %0, t;}" : "=r"(a) : "l"(p));
    return a;
}
__device__ __forceinline__ void cp16(uint32_t d, const void* s) {
    asm volatile("cp.async.cg.shared.global [%0], [%1], 16;" :: "r"(d), "l"(s));
}
__device__ __forceinline__ void cp_commit() { asm volatile("cp.async.commit_group;"); }
template <int N>
__device__ __forceinline__ void cp_wait() { asm volatile("cp.async.wait_group %0;" :: "n"(N)); }

__device__ __forceinline__ void ldsm4(uint32_t& r0, uint32_t& r1, uint32_t& r2, uint32_t& r3,
                                      uint32_t a) {
    asm volatile("ldmatrix.sync.aligned.m8n8.x4.shared.b16 {%0,%1,%2,%3}, [%4];"
                 : "=r"(r0), "=r"(r1), "=r"(r2), "=r"(r3) : "r"(a));
}
__device__ __forceinline__ void mma16816(float c[4], const uint32_t a[4], const uint32_t b[2]) {
    asm volatile(
        "mma.sync.aligned.m16n8k16.row.col.f32.f16.f16.f32 "
        "{%0,%1,%2,%3},{%4,%5,%6,%7},{%8,%9},{%0,%1,%2,%3};"
        : "+f"(c[0]), "+f"(c[1]), "+f"(c[2]), "+f"(c[3])
        : "r"(a[0]), "r"(a[1]), "r"(a[2]), "r"(a[3]), "r"(b[0]), "r"(b[1]));
}

// ------------------------------ GEMM kernel --------------------------------
// C[mb:mb+128, n0:n0+128] = A @ W[n,:]^T  (A, W fp16; C fp16, fp32 accum)
__global__ __launch_bounds__(128, 2)
void gemm_f16(const __half* __restrict__ Ag, const __half* __restrict__ Wg,
              __half* __restrict__ Cb, int phase, int recur)
{
    extern __shared__ __align__(128) char smem[];
    const uint32_t sb = smem_u32(smem);
    const int tid = threadIdx.x, warp = tid >> 5, lane = tid & 31;
    const int n0 = blockIdx.x * BN, mb = blockIdx.y * BM, dz = blockIdx.z;

    const __half* A = Ag + (recur ? (size_t)((dz * 2 + phase) * B_ + mb) * K_
                                  : (size_t)mb * K_);
    const __half* W = Wg + (size_t)n0 * K_;
    __half* C = Cb + (size_t)dz * B_ * N3;

    // warp tile: 64 x 64  (warp grid 2 x 2)
    const int wm = (warp & 1) * 64, wn = (warp >> 1) * 64;
    const uint32_t aFrag = sb + (uint32_t)(wm + (lane & 15)) * ROWB + ((lane >> 4) & 1) * 16;
    const uint32_t bFrag = sb + A_BYTES +
        (uint32_t)(wn + ((lane >> 4) & 1) * 8 + (lane & 7)) * ROWB + ((lane >> 3) & 1) * 16;

    float acc[4][8][4];
#pragma unroll
    for (int a = 0; a < 4; ++a)
#pragma unroll
        for (int b = 0; b < 8; ++b)
#pragma unroll
            for (int c = 0; c < 4; ++c) acc[a][b][c] = 0.f;

    // fill: 128 rows x 8 chunks(16B) for A and B; 8 per thread each (128 thr)
#define FILL(S, KT)                                                           \
    {                                                                         \
        _Pragma("unroll")                                                     \
        for (int i = 0; i < 8; ++i) {                                         \
            int c = tid + 128 * i;                                            \
            int row = c >> 3, col = c & 7;                                    \
            uint32_t d = sb + (S) * STAGE + row * ROWB + col * 16;            \
            cp16(d, A + (size_t)row * K_ + (KT) * BK + col * 8);              \
            cp16(d + A_BYTES, W + (size_t)row * K_ + (KT) * BK + col * 8);    \
        }                                                                     \
    }

#pragma unroll
    for (int s = 0; s < NST - 1; ++s) { FILL(s, s); cp_commit(); }

    int st = 0;
    for (int kt = 0; kt < NKT; ++kt) {
        cp_wait<NST - 2>();
        __syncthreads();
        if (kt + NST - 1 < NKT) {
            int fs = st + 2; if (fs >= NST) fs -= NST;
            FILL(fs, kt + NST - 1);
        }
        cp_commit();

        const uint32_t aS = aFrag + st * STAGE;
        const uint32_t bS = bFrag + st * STAGE;
#pragma unroll
        for (int ks = 0; ks < 4; ++ks) {
            uint32_t af[4][4], bf[8][2];
#pragma unroll
            for (int mi = 0; mi < 4; ++mi)
                ldsm4(af[mi][0], af[mi][1], af[mi][2], af[mi][3],
                      aS + mi * 16 * ROWB + ks * 32);
#pragma unroll
            for (int nj = 0; nj < 4; ++nj)
                ldsm4(bf[2 * nj][0], bf[2 * nj][1], bf[2 * nj + 1][0], bf[2 * nj + 1][1],
                      bS + nj * 16 * ROWB + ks * 32);
#pragma unroll
            for (int mi = 0; mi < 4; ++mi)
#pragma unroll
                for (int ni = 0; ni < 8; ++ni)
                    mma16816(acc[mi][ni], af[mi], bf[ni]);
        }
        if (++st == NST) st = 0;
    }
#undef FILL

    // epilogue: fp16 stores (half2 per fragment row-pair)
    __half* crow = C + (size_t)(mb + wm + (lane >> 2)) * N3 + n0 + wn + (lane & 3) * 2;
#pragma unroll
    for (int mi = 0; mi < 4; ++mi) {
#pragma unroll
        for (int ni = 0; ni < 8; ++ni) {
            *reinterpret_cast<__half2*>(crow + (size_t)(mi * 16) * N3 + ni * 8) =
                __floats2half2_rn(acc[mi][ni][0], acc[mi][ni][1]);
            *reinterpret_cast<__half2*>(crow + (size_t)(mi * 16 + 8) * N3 + ni * 8) =
                __floats2half2_rn(acc[mi][ni][2], acc[mi][ni][3]);
        }
    }
}

// ------------------------------ gate kernel --------------------------------
__device__ __forceinline__ float sigmoidf_(float x) { return 1.f / (1.f + expf(-x)); }

__global__ __launch_bounds__(256)
void gate_kernel(const float* __restrict__ b_izr, const float* __restrict__ b_hzr,
                 const float* __restrict__ b_it,  const float* __restrict__ b_ht,
                 float* __restrict__ out, int s, int phase)
{
    const int d   = blockIdx.z;
    const int idx = blockIdx.x * blockDim.x + threadIdx.x;
    const int j4  = idx << 2;
    const int b   = j4 >> 10;
    const int j   = j4 & (H_ - 1);
    const int time = (d == 0) ? s : (T_ - 1 - s);
    const int tout = (d == 0) ? (T_ - 1 - s) : s;

    const __half* gx = g_gx16 + ((size_t)b * T_ + time) * N3;
    const __half* gh = g_gh16 + (size_t)d * B_ * N3 + (size_t)b * N3;
    const float*  hp = g_h + ((size_t)d * 2 + phase) * B_ * H_ + (size_t)b * H_;
    const size_t hoff = ((size_t)d * 2 + (phase ^ 1)) * B_ * H_ + (size_t)b * H_ + j;

#define LDH4(p) (*reinterpret_cast<const uint2*>(p))
    uint2 uxr = LDH4(gx + j),          uxz = LDH4(gx + H_ + j),      uxt = LDH4(gx + 2 * H_ + j);
    uint2 uhr = LDH4(gh + j),          uhz = LDH4(gh + H_ + j),      uht = LDH4(gh + 2 * H_ + j);
#undef LDH4
    float4 bir = *(const float4*)(b_izr + j);
    float4 biz = *(const float4*)(b_izr + H_ + j);
    float4 bhr = *(const float4*)(b_hzr + j);
    float4 bhz = *(const float4*)(b_hzr + H_ + j);
    float4 bti = *(const float4*)(b_it + j);
    float4 bth = *(const float4*)(b_ht + j);
    float4 h   = *(const float4*)(hp + j);

    float2 xr0 = __half22float2(*reinterpret_cast<__half2*>(&uxr.x));
    float2 xr1 = __half22float2(*reinterpret_cast<__half2*>(&uxr.y));
    float2 xz0 = __half22float2(*reinterpret_cast<__half2*>(&uxz.x));
    float2 xz1 = __half22float2(*reinterpret_cast<__half2*>(&uxz.y));
    float2 xt0 = __half22float2(*reinterpret_cast<__half2*>(&uxt.x));
    float2 xt1 = __half22float2(*reinterpret_cast<__half2*>(&uxt.y));
    float2 hr0 = __half22float2(*reinterpret_cast<__half2*>(&uhr.x));
    float2 hr1 = __half22float2(*reinterpret_cast<__half2*>(&uhr.y));
    float2 hz0 = __half22float2(*reinterpret_cast<__half2*>(&uhz.x));
    float2 hz1 = __half22float2(*reinterpret_cast<__half2*>(&uhz.y));
    float2 ht0 = __half22float2(*reinterpret_cast<__half2*>(&uht.x));
    float2 ht1 = __half22float2(*reinterpret_cast<__half2*>(&uht.y));

    float4 nh;
#define GATE(c, GXR, GHR, GXZ, GHZ, GXT, GHT)                               \
    {                                                                       \
        float rg = sigmoidf_(GXR + GHR + bir.c + bhr.c);                    \
        float zg = sigmoidf_(GXZ + GHZ + biz.c + bhz.c);                    \
        float ht = tanhf(GXT + bti.c + rg * (GHT + bth.c));                 \
        nh.c = zg * ht + (1.f - zg) * h.c;                                  \
    }
    GATE(x, xr0.x, hr0.x, xz0.x, hz0.x, xt0.x, ht0.x)
    GATE(y, xr0.y, hr0.y, xz0.y, hz0.y, xt0.y, ht0.y)
    GATE(z, xr1.x, hr1.x, xz1.x, hz1.x, xt1.x, ht1.x)
    GATE(w, xr1.y, hr1.y, xz1.y, hz1.y, xt1.y, ht1.y)
#undef GATE

    *(float4*)(g_h + hoff) = nh;
    __half2 p0 = __floats2half2_rn(nh.x, nh.y);
    __half2 p1 = __floats2half2_rn(nh.z, nh.w);
    uint2 u; u.x = *reinterpret_cast<uint32_t*>(&p0); u.y = *reinterpret_cast<uint32_t*>(&p1);
    *reinterpret_cast<uint2*>(g_h16 + hoff) = u;
    *(float4*)(out + ((size_t)b * T_ + tout) * (2 * H_) + (size_t)d * H_ + j) = nh;
}

// ------------------------------ small kernels ------------------------------
__global__ void cvt16(const float* __restrict__ s, __half* __restrict__ d, int n4)
{
    int i = blockIdx.x * blockDim.x + threadIdx.x;
    if (i < n4) {
        float4 v = reinterpret_cast<const float4*>(s)[i];
        __half2 p0 = __floats2half2_rn(v.x, v.y);
        __half2 p1 = __floats2half2_rn(v.z, v.w);
        uint2 u; u.x = *reinterpret_cast<uint32_t*>(&p0); u.y = *reinterpret_cast<uint32_t*>(&p1);
        reinterpret_cast<uint2*>(d)[i] = u;
    }
}

__global__ void init_h(const float* __restrict__ h0, const float* __restrict__ bih0)
{
    size_t i = (size_t)blockIdx.x * blockDim.x + threadIdx.x;
    if (i < (size_t)B_ * H_) {
        float a = h0[i], b = bih0[i];
        g_h[i] = a;
        g_h[(size_t)2 * B_ * H_ + i] = b;
        g_h16[i] = __float2half_rn(a);
        g_h16[(size_t)2 * B_ * H_ + i] = __float2half_rn(b);
    }
}

// ------------------------------ host side ----------------------------------
extern "C" void kernel_launch(void* const* d_in, const int* in_sizes, int n_in,
                              void* d_out, int out_size)
{
    const float* x     = (const float*)d_in[0];
    const float* h0    = (const float*)d_in[1];
    const float* bih0  = (const float*)d_in[2];
    const float* W_izr = (const float*)d_in[3];
    const float* b_izr = (const float*)d_in[4];
    const float* W_hzr = (const float*)d_in[5];
    const float* b_hzr = (const float*)d_in[6];
    const float* W_it  = (const float*)d_in[7];
    const float* b_it  = (const float*)d_in[8];
    const float* W_ht  = (const float*)d_in[9];
    const float* b_ht  = (const float*)d_in[10];
    float* out = (float*)d_out;
    (void)in_sizes; (void)n_in; (void)out_size;

    void *p_gx = nullptr, *p_gh = nullptr, *p_x16 = nullptr, *p_h16 = nullptr,
         *p_wx = nullptr, *p_wh = nullptr;
    cudaGetSymbolAddress(&p_gx, g_gx16);
    cudaGetSymbolAddress(&p_gh, g_gh16);
    cudaGetSymbolAddress(&p_x16, g_x16);
    cudaGetSymbolAddress(&p_h16, g_h16);
    cudaGetSymbolAddress(&p_wx, g_wx16);
    cudaGetSymbolAddress(&p_wh, g_wh16);

    cudaFuncSetAttribute(gemm_f16, cudaFuncAttributeMaxDynamicSharedMemorySize, SMEM_BYTES);

    // fp16 conversions
    const int WN4 = 2 * H_ * K_ / 4, WN4b = H_ * K_ / 4, XN4 = B_ * T_ * K_ / 4;
    cvt16<<<(WN4 + 255) / 256, 256>>>(W_izr, (__half*)p_wx, WN4);
    cvt16<<<(WN4b + 255) / 256, 256>>>(W_it, (__half*)p_wx + (size_t)2 * H_ * K_, WN4b);
    cvt16<<<(WN4 + 255) / 256, 256>>>(W_hzr, (__half*)p_wh, WN4);
    cvt16<<<(WN4b + 255) / 256, 256>>>(W_ht, (__half*)p_wh + (size_t)2 * H_ * K_, WN4b);
    cvt16<<<(XN4 + 255) / 256, 256>>>(x, (__half*)p_x16, XN4);
    init_h<<<(B_ * H_ + 255) / 256, 256>>>(h0, bih0);

    // Gx = X @ [W_izr; W_it]^T over all (b, t)
    gemm_f16<<<dim3(N3 / BN, (B_ * T_) / BM, 1), 128, SMEM_BYTES>>>(
        (const __half*)p_x16, (const __half*)p_wx, (__half*)p_gx, 0, 0);

    // 16 sequential steps, both directions per launch
    int phase = 0;
    for (int s = 0; s < T_; ++s) {
        gemm_f16<<<dim3(N3 / BN, B_ / BM, 2), 128, SMEM_BYTES>>>(
            (const __half*)p_h16, (const __half*)p_wh, (__half*)p_gh, phase, 1);
        gate_kernel<<<dim3((B_ * H_) / (256 * 4), 1, 2), 256>>>(
            b_izr, b_hzr, b_it, b_ht, out, s, phase);
        phase ^= 1;
    }
}